// round 13
// baseline (speedup 1.0000x reference)
#include <cuda_runtime.h>

// Batched active-set (water-filling) projection — 2 warps/row, Newton per
// phase with analytic warm start + fused phase transition.
//
// Within each phase the reference's fixed point is the unique root of a
// monotone piecewise-linear equation; Newton (exact solve on the current
// threshold set) converges to that root globally from ANY start, and
// count-equality between consecutive scans implies set-equality (threshold
// sets are nested in T). So the start threshold only affects iteration
// count, never the converged result:
//   phase 0 warm start: Gaussian-expected root  T ~= -0.1883 + 0.0017*s0
//   phase 1 warm start: T0 - 0.26, evaluated inside the transition pass
// Per iteration: 16-elem scan/lane, REDUX.ADD partials (count + 2^18 fixed
// point sum), one int4 smem exchange + one __syncthreads (double-buffered).

#define NCOLS 1024
#define EPL 16
#define THREADS 64

#define SCALEF   262144.0f              // 2^18
#define INVSCALE (1.0f / 262144.0f)

__global__ __launch_bounds__(THREADS)
void proj_kernel(const float* __restrict__ y,
                 const float* __restrict__ upper,
                 float* __restrict__ out) {
    const int t   = threadIdx.x;
    const int wid = t >> 5;
    const int row = blockIdx.x;

    __shared__ int4 slot[2][2];          // [buffer][warp]
    int buf = 0;

    const float NEG_INF = __int_as_float(0xff800000);

    float yv[EPL], uv[EPL];
    {
        const float4* yrow = reinterpret_cast<const float4*>(y + (size_t)row * NCOLS);
        const float4* urow = reinterpret_cast<const float4*>(upper);
        #pragma unroll
        for (int k = 0; k < 4; k++) {
            const float4 a = yrow[t + 64 * k];
            const float4 b = urow[t + 64 * k];
            yv[4*k+0]=a.x; yv[4*k+1]=a.y; yv[4*k+2]=a.z; yv[4*k+3]=a.w;
            uv[4*k+0]=b.x; uv[4*k+1]=b.y; uv[4*k+2]=b.z; uv[4*k+3]=b.w;
        }
    }

    auto exchange = [&](int4 v) -> int4 {
        if ((t & 31) == 0) slot[buf][wid] = v;
        __syncthreads();
        const int4 o = slot[buf][wid ^ 1];
        buf ^= 1;
        return o;
    };

    // ---- s0 = sum(y) ----
    float base0, s0f;
    {
        float a0=0.f,a1=0.f,a2=0.f,a3=0.f;
        #pragma unroll
        for (int e = 0; e < EPL; e += 4) {
            a0 += yv[e+0]; a1 += yv[e+1]; a2 += yv[e+2]; a3 += yv[e+3];
        }
        const int h  = __float2int_rn((a0+a1)*SCALEF) + __float2int_rn((a2+a3)*SCALEF);
        const int hr = __reduce_add_sync(0xffffffffu, h);
        const int4 o = exchange(make_int4(hr, 0, 0, 0));
        const int si = hr + o.x;
        s0f   = (float)si * INVSCALE;
        base0 = 512.0f - s0f;
    }

    // ---- phase 0: Newton on lower set {y < T}, warm start ----
    float T = fmaf(s0f, 0.0017f, -0.1883f);
    float maskT0;
    {
        int prev = -1;
        int itc  = 0;
        for (;;) {
            int   c0=0,c1=0;
            float d0=0.f,d1=0.f,d2=0.f,d3=0.f;
            #pragma unroll
            for (int e = 0; e < EPL; e += 4) {
                const bool p0 = yv[e+0] < T, p1 = yv[e+1] < T,
                           p2 = yv[e+2] < T, p3 = yv[e+3] < T;
                c0 += p0 + p2; c1 += p1 + p3;
                d0 += p0 ? yv[e+0] : 0.f; d1 += p1 ? yv[e+1] : 0.f;
                d2 += p2 ? yv[e+2] : 0.f; d3 += p3 ? yv[e+3] : 0.f;
            }
            const int dh  = __float2int_rn((d0+d1)*SCALEF) + __float2int_rn((d2+d3)*SCALEF);
            const int crh = __reduce_add_sync(0xffffffffu, c0 + c1);
            const int drh = __reduce_add_sync(0xffffffffu, dh);
            const int4 o  = exchange(make_int4(crh, drh, 0, 0));
            const int cr  = crh + o.x;
            const float D = (float)(drh + o.y) * INVSCALE;

            if (cr == prev || ++itc >= 16) { maskT0 = T; break; }
            prev = cr;
            T = -__fdividef(base0 + D, fmaxf(1024.0f - (float)cr, 1.0f));
        }
    }
    const float fill0 = -T;   // consistent with maskT0 at exit

    // ---- fused transition + phase-1 warm-start scan ----
    // yv <- d = y-u (free) / -INF (lower). Also evaluate the upper scan at
    // T1ws = maskT0 - 0.26 (warm start), and gather n_lo / sum_lower(y).
    const float T1ws = maskT0 - 0.26f;
    float base1, n1;
    int   prev1;
    {
        int   nlo=0, chi=0;
        float s0a=0.f, s1a=0.f, h0=0.f, h1=0.f;
        #pragma unroll
        for (int e = 0; e < EPL; e++) {
            const bool lo = yv[e] < maskT0;
            const float d = yv[e] - uv[e];
            nlo += lo;
            if (e & 1) s1a += lo ? yv[e] : 0.f; else s0a += lo ? yv[e] : 0.f;
            const float dn = lo ? NEG_INF : d;
            yv[e] = dn;
            const bool hi = dn > T1ws;
            chi += hi;
            if (e & 1) h1 += hi ? dn : 0.f; else h0 += hi ? dn : 0.f;
        }
        const int pc  = (nlo << 16) | chi;                 // both <= 512/lane-sum
        const int sli = __float2int_rn(s0a*SCALEF) + __float2int_rn(s1a*SCALEF);
        const int dhi = __float2int_rn(h0*SCALEF)  + __float2int_rn(h1*SCALEF);
        const int pcr = __reduce_add_sync(0xffffffffu, pc);
        const int slr = __reduce_add_sync(0xffffffffu, sli);
        const int dhr = __reduce_add_sync(0xffffffffu, dhi);
        const int4 o  = exchange(make_int4(pcr, slr, dhr, 0));
        const int pct = pcr + o.x;
        const int nloT = pct >> 16;
        const int chiT = pct & 0xffff;
        const float slo = (float)(slr + o.y) * INVSCALE;
        const float dhS = (float)(dhr + o.z) * INVSCALE;

        base1 = base0 + slo;
        n1    = 1024.0f - (float)nloT;
        prev1 = chiT;
        // first Newton update from the warm-start scan
        T = -__fdividef(base1 + dhS, fmaxf(n1 - (float)chiT, 1.0f));
    }

    // ---- phase 1: Newton on upper set {d > T} ----
    float maskT1;
    {
        int itc = 0;
        for (;;) {
            int   c0=0,c1=0;
            float d0=0.f,d1=0.f,d2=0.f,d3=0.f;
            #pragma unroll
            for (int e = 0; e < EPL; e += 4) {
                const bool p0 = yv[e+0] > T, p1 = yv[e+1] > T,
                           p2 = yv[e+2] > T, p3 = yv[e+3] > T;
                c0 += p0 + p2; c1 += p1 + p3;
                d0 += p0 ? yv[e+0] : 0.f; d1 += p1 ? yv[e+1] : 0.f;
                d2 += p2 ? yv[e+2] : 0.f; d3 += p3 ? yv[e+3] : 0.f;
            }
            const int dh  = __float2int_rn((d0+d1)*SCALEF) + __float2int_rn((d2+d3)*SCALEF);
            const int crh = __reduce_add_sync(0xffffffffu, c0 + c1);
            const int arh = __reduce_add_sync(0xffffffffu, dh);
            const int4 o  = exchange(make_int4(crh, arh, 0, 0));
            const int cr  = crh + o.x;
            const float A = (float)(arh + o.y) * INVSCALE;

            if (cr == prev1 || ++itc >= 16) { maskT1 = T; break; }
            prev1 = cr;
            T = -__fdividef(base1 + A, fmaxf(n1 - (float)cr, 1.0f));
        }
    }
    const float fill1 = -T;   // consistent with maskT1 at exit
    (void)fill0;

    // ---- epilogue: lower (-INF) -> 0; upper (d > T1) -> u; free -> d+u+fill
    float4* orow = reinterpret_cast<float4*>(out + (size_t)row * NCOLS);
    #pragma unroll
    for (int k = 0; k < 4; k++) {
        float o4[4];
        #pragma unroll
        for (int j = 0; j < 4; j++) {
            const int e = 4 * k + j;
            const float d = yv[e];
            o4[j] = (d == NEG_INF) ? 0.0f
                  : ((d > maskT1) ? uv[e] : d + uv[e] + fill1);
        }
        float4 v; v.x=o4[0]; v.y=o4[1]; v.z=o4[2]; v.w=o4[3];
        orow[t + 64 * k] = v;
    }
}

extern "C" void kernel_launch(void* const* d_in, const int* in_sizes, int n_in,
                              void* d_out, int out_size) {
    const float* y     = (const float*)d_in[0];
    const float* upper = (const float*)d_in[1];
    float*       out   = (float*)d_out;
    const int rows = in_sizes[0] / NCOLS;    // 2048
    proj_kernel<<<rows, THREADS>>>(y, upper, out);
}

// round 15
// speedup vs baseline: 1.1195x; 1.1195x over previous
#include <cuda_runtime.h>

// Batched active-set (water-filling) projection — warp-per-row, threshold-set
// Newton (the 10.7us R10 winner) + analytic warm starts.
//
// Within each phase the reference's fixed point is the unique root of a
// monotone piecewise-linear equation; Newton (exact solve on the current
// threshold set) reaches it finitely from ANY start, so the start only
// affects scan count, never the converged set (empirically confirmed at
// rel_err 1e-7 in an earlier warm-started round):
//   phase 0: Gaussian-expected root  fill ~= 0.19 - 0.00168*s0  (~2-3 scans)
//   phase 1: start at fill0 + 0.10                              (~saves 1)
// All arithmetic that reaches decisions or outputs is exact (float compares,
// 2^18 fixed-point REDUX sums, __fdividef water level) — identical to R10.
//
// Phase 0: lower set {y < -fill}. Phase 1: upper set {d=y-u > -fill} over
// the frozen complement; lower-clamps poisoned to -INF in yv. upper lives
// in shared memory. Warp-private: no barriers in the loops.

#define NCOLS 1024
#define EPL 32
#define WARPS_PER_BLOCK 2
#define THREADS (WARPS_PER_BLOCK * 32)

#define SCALEF   262144.0f              // 2^18
#define INVSCALE (1.0f / 262144.0f)

__global__ __launch_bounds__(THREADS)
void proj_kernel(const float* __restrict__ y,
                 const float* __restrict__ upper,
                 float* __restrict__ out) {
    const int lane = threadIdx.x & 31;
    const int row  = blockIdx.x * WARPS_PER_BLOCK + (threadIdx.x >> 5);

    __shared__ float su[NCOLS];
    {
        const float4* u4 = reinterpret_cast<const float4*>(upper);
        float4*       s4 = reinterpret_cast<float4*>(su);
        #pragma unroll
        for (int k = 0; k < 4; k++)
            s4[threadIdx.x + THREADS * k] = u4[threadIdx.x + THREADS * k];
    }
    __syncthreads();   // one-time; warps independent afterwards

    const float NEG_INF = __int_as_float(0xff800000);

    float yv[EPL];
    {
        const float4* yrow = reinterpret_cast<const float4*>(y + (size_t)row * NCOLS);
        #pragma unroll
        for (int k = 0; k < 8; k++) {
            const float4 a = yrow[lane + 32 * k];
            yv[4*k+0]=a.x; yv[4*k+1]=a.y; yv[4*k+2]=a.z; yv[4*k+3]=a.w;
        }
    }

    // s0 = sum(y): 4-way tree, parallel F2I, REDUX
    float s0;
    {
        float a0=0.f, a1=0.f, a2=0.f, a3=0.f;
        #pragma unroll
        for (int e = 0; e < EPL; e += 4) {
            a0 += yv[e+0]; a1 += yv[e+1]; a2 += yv[e+2]; a3 += yv[e+3];
        }
        const int i0 = __float2int_rn(a0 * SCALEF), i1 = __float2int_rn(a1 * SCALEF);
        const int i2 = __float2int_rn(a2 * SCALEF), i3 = __float2int_rn(a3 * SCALEF);
        const int si = __reduce_add_sync(0xffffffffu, (i0+i1)+(i2+i3));
        s0 = (float)si * INVSCALE;
    }

    const float base0 = 512.0f - s0;
    // analytic warm start (Gaussian-expected phase-0 root); Newton converges
    // to the unique fixed point from any start.
    float fill = fmaf(s0, -0.00168f, 0.19f);

    int   it = 0;
    float maskT0 = 0.0f;
    bool  p0conv = false;
    float cntF = 0.0f, dsF = 0.0f;

    // ---- phase 0: lower clamps (threshold scan on y) ----
    {
        int prev = -1;
        for (;;) {
            ++it;
            const float T = -fill;
            int   c0=0,c1=0,c2=0,c3=0;
            float d0=0.f,d1=0.f,d2=0.f,d3=0.f;
            #pragma unroll
            for (int e = 0; e < EPL; e += 4) {
                const bool p0 = yv[e+0] < T, p1 = yv[e+1] < T,
                           p2 = yv[e+2] < T, p3 = yv[e+3] < T;
                c0 += p0; c1 += p1; c2 += p2; c3 += p3;
                d0 += p0 ? yv[e+0] : 0.f; d1 += p1 ? yv[e+1] : 0.f;
                d2 += p2 ? yv[e+2] : 0.f; d3 += p3 ? yv[e+3] : 0.f;
            }
            const int j0 = __float2int_rn(d0 * SCALEF), j1 = __float2int_rn(d1 * SCALEF);
            const int j2 = __float2int_rn(d2 * SCALEF), j3 = __float2int_rn(d3 * SCALEF);
            const int cr = __reduce_add_sync(0xffffffffu, (c0+c1)+(c2+c3));
            const int dr = __reduce_add_sync(0xffffffffu, (j0+j1)+(j2+j3));
            const float D = (float)dr * INVSCALE;
            maskT0 = T; cntF = (float)cr; dsF = D;
            if (cr == prev) { p0conv = true; break; }   // set stable -> converged
            prev = cr;
            fill = __fdividef(base0 + D, fmaxf(1024.0f - (float)cr, 1.0f));
            if (it >= 32) break;                         // safety cap
        }
    }

    float4* orow = reinterpret_cast<float4*>(out + (size_t)row * NCOLS);
    const float4* su4 = reinterpret_cast<const float4*>(su);

    if (p0conv && it < 32) {
        // phase transition: yv <- d = y-u (free) / -INF (lower-clamped)
        #pragma unroll
        for (int k = 0; k < 8; k++) {
            const float4 u4 = su4[lane + 32 * k];
            const float uu[4] = {u4.x, u4.y, u4.z, u4.w};
            #pragma unroll
            for (int j = 0; j < 4; j++) {
                const int e = 4 * k + j;
                yv[e] = (yv[e] < maskT0) ? NEG_INF : (yv[e] - uu[j]);
            }
        }
        const float base1 = base0 + dsF;
        const float n1    = 1024.0f - cntF;

        // phase-1 warm start: fill rises in phase 1; bump toward the expected
        // root (Newton converges from either side).
        fill += 0.10f;

        // ---- phase 1: upper clamps (threshold scan on d) ----
        // poisoned entries are -INF -> (d > T) false; never selected.
        float maskT1 = 0.0f;
        {
            int prev1 = -1;
            for (;;) {
                ++it;
                const float T = -fill;
                int   c0=0,c1=0,c2=0,c3=0;
                float d0=0.f,d1=0.f,d2=0.f,d3=0.f;
                #pragma unroll
                for (int e = 0; e < EPL; e += 4) {
                    const bool p0 = yv[e+0] > T, p1 = yv[e+1] > T,
                               p2 = yv[e+2] > T, p3 = yv[e+3] > T;
                    c0 += p0; c1 += p1; c2 += p2; c3 += p3;
                    d0 += p0 ? yv[e+0] : 0.f; d1 += p1 ? yv[e+1] : 0.f;
                    d2 += p2 ? yv[e+2] : 0.f; d3 += p3 ? yv[e+3] : 0.f;
                }
                const int j0 = __float2int_rn(d0 * SCALEF), j1 = __float2int_rn(d1 * SCALEF);
                const int j2 = __float2int_rn(d2 * SCALEF), j3 = __float2int_rn(d3 * SCALEF);
                const int cr = __reduce_add_sync(0xffffffffu, (c0+c1)+(c2+c3));
                const int ar = __reduce_add_sync(0xffffffffu, (j0+j1)+(j2+j3));
                const float A = (float)ar * INVSCALE;
                maskT1 = T;
                if (cr == prev1) break;
                prev1 = cr;
                fill = __fdividef(base1 + A, fmaxf(n1 - (float)cr, 1.0f));
                if (it >= 64) break;
            }
        }

        // epilogue: yv holds d. lower (-INF) -> 0; upper (d > T1) -> u;
        // free -> y + fill = d + u + fill
        #pragma unroll
        for (int k = 0; k < 8; k++) {
            const float4 u4 = su4[lane + 32 * k];
            const float uu[4] = {u4.x, u4.y, u4.z, u4.w};
            float o4[4];
            #pragma unroll
            for (int j = 0; j < 4; j++) {
                const int e = 4 * k + j;
                const float d = yv[e];
                o4[j] = (d == NEG_INF) ? 0.0f
                      : ((d > maskT1) ? uu[j] : d + uu[j] + fill);
            }
            float4 v; v.x=o4[0]; v.y=o4[1]; v.z=o4[2]; v.w=o4[3];
            orow[lane + 32 * k] = v;
        }
    } else {
        // safety path (cap hit in phase 0)
        #pragma unroll
        for (int k = 0; k < 8; k++) {
            float o4[4];
            #pragma unroll
            for (int j = 0; j < 4; j++) {
                const int e = 4 * k + j;
                o4[j] = (yv[e] < maskT0) ? 0.0f : yv[e] + fill;
            }
            float4 v; v.x=o4[0]; v.y=o4[1]; v.z=o4[2]; v.w=o4[3];
            orow[lane + 32 * k] = v;
        }
    }
}

extern "C" void kernel_launch(void* const* d_in, const int* in_sizes, int n_in,
                              void* d_out, int out_size) {
    const float* y     = (const float*)d_in[0];
    const float* upper = (const float*)d_in[1];
    float*       out   = (float*)d_out;
    const int rows   = in_sizes[0] / NCOLS;                      // 2048
    const int blocks = (rows + WARPS_PER_BLOCK - 1) / WARPS_PER_BLOCK;
    proj_kernel<<<blocks, THREADS>>>(y, upper, out);
}